// round 11
// baseline (speedup 1.0000x reference)
#include <cuda_runtime.h>
#include <cuda_fp16.h>
#include <math.h>
#include <stdint.h>

#define SEQ 2048
#define DM  1024
#define NB  4

static constexpr size_t NQ  = (size_t)NB * SEQ * DM;    //  8388608
static constexpr size_t NSS = (size_t)NB * SEQ * SEQ;   // 16777216
static constexpr size_t NP  = (size_t)SEQ * DM;         //  2097152
static constexpr size_t NU  = (size_t)DM * DM;          //  1048576

// ---- scratch (static device globals; no allocation) ----
__device__ __half g_qhi[NQ],  g_qlo[NQ];
__device__ __half g_khi[NQ],  g_klo[NQ];
__device__ __half g_vthi[NQ];
__device__ __half g_ahi[NSS];
__device__ __half g_pehi[NP];
__device__ __half g_uqt[NU],  g_ukt[NU];
__device__ __half g_qpe[NP],  g_kpe[NP];
__device__ float  g_bias[(size_t)SEQ * SEQ];
__device__ float  g_scores[NSS];

// ------------------------------- PTX helpers -------------------------------
__device__ __forceinline__ uint32_t s2u(const void* p) {
    uint32_t a;
    asm("{ .reg .u64 t; cvta.to.shared.u64 t, %1; cvt.u32.u64 %0, t; }"
        : "=r"(a) : "l"(p));
    return a;
}
__device__ __forceinline__ void cpa16(uint32_t dst, const void* src) {
    asm volatile("cp.async.cg.shared.global [%0], [%1], 16;" :: "r"(dst), "l"(src) : "memory");
}
#define LDSM4(r, addr) \
    asm volatile("ldmatrix.sync.aligned.m8n8.x4.shared.b16 {%0,%1,%2,%3}, [%4];" \
        : "=r"((r)[0]), "=r"((r)[1]), "=r"((r)[2]), "=r"((r)[3]) : "r"(addr))
#define MMA_F16_F32(d, a, b0, b1) \
    asm volatile("mma.sync.aligned.m16n8k16.row.col.f32.f16.f16.f32 " \
        "{%0,%1,%2,%3}, {%4,%5,%6,%7}, {%8,%9}, {%0,%1,%2,%3};" \
        : "+f"((d)[0]), "+f"((d)[1]), "+f"((d)[2]), "+f"((d)[3]) \
        : "r"((a)[0]), "r"((a)[1]), "r"((a)[2]), "r"((a)[3]), "r"(b0), "r"(b1))

// ---------------------------------------------------------------------------
// fp16 HMMA GEMM: C[M,N] = alpha * (sum_passes A_p @ B_p^T [+ bias])
//   PASSES==3: Ahi*Bhi + Ahi*Blo + Alo*Bhi (pass-major MMA order, reuse dist 16)
//   PASSES==1: Ahi*Bhi
//   OUTMODE: 0 = fp32 row-major (+bias, *alpha); 1 = fp16 row-major
//   CTA tile 128x128, BK=32, 256 threads (8 warps, warp tile 32x64),
//   2-stage cp.async pipeline, 80B-padded SMEM rows (conflict-free ldmatrix).
// ---------------------------------------------------------------------------
template<int PASSES, int OUTMODE>
__global__ void __launch_bounds__(256, 1)
hgemm(const __half* __restrict__ Ahi, const __half* __restrict__ Alo,
      const __half* __restrict__ Bhi, const __half* __restrict__ Blo,
      void* __restrict__ Cp, const float* __restrict__ bias, int Kt, int Ng,
      long long aStr, long long bStr, long long cStr, float alpha)
{
    extern __shared__ __align__(128) char smem[];
    constexpr int RSTRIDE = 80;                     // 32 f16 + 16B pad
    constexpr int TSZ = 128 * RSTRIDE;              // 10240 B per tile
    constexpr int NT  = (PASSES == 3) ? 4 : 2;      // tiles per stage
    constexpr int STAGE = NT * TSZ;

    const uint32_t sb = s2u(smem);
    const int tid = threadIdx.x;
    const int lane = tid & 31;
    const int wid = tid >> 5;
    const int warp_m = wid & 3;                      // 4 warps along M
    const int warp_n = wid >> 2;                     // 2 warps along N
    const int bm = blockIdx.y * 128, bn = blockIdx.x * 128, bz = blockIdx.z;
    const int NC = Kt >> 5;                          // chunks of BK=32

    const __half* Abase[2] = { Ahi + (long long)bz * aStr,
                               (PASSES == 3) ? Alo + (long long)bz * aStr : nullptr };
    const __half* Bbase[2] = { Bhi + (long long)bz * bStr,
                               (PASSES == 3) ? Blo + (long long)bz * bStr : nullptr };

    auto load_chunk = [&](int c) {
        const uint32_t stg = sb + (c & 1) * STAGE;
        const long long kc = (long long)c << 5;
        #pragma unroll
        for (int it = 0; it < NT * 2; it++) {
            const int idx = tid + it * 256;          // NT*512 chunks of 16B
            const int t4  = idx >> 9;                // tile id
            const int r   = (idx >> 2) & 127;        // row in tile
            const int c16 = idx & 3;                 // 16B chunk in row
            const __half* src;
            int rowg;
            if (PASSES == 3) {
                if (t4 < 2) { src = Abase[t4]; rowg = bm + r; }
                else        { src = Bbase[t4 - 2]; rowg = bn + r; }
            } else {
                if (t4 == 0) { src = Abase[0]; rowg = bm + r; }
                else         { src = Bbase[0]; rowg = bn + r; }
            }
            cpa16(stg + t4 * TSZ + r * RSTRIDE + c16 * 16,
                  src + (long long)rowg * Kt + kc + c16 * 8);
        }
        asm volatile("cp.async.commit_group;" ::: "memory");
    };

    float acc[2][8][4];
    #pragma unroll
    for (int f = 0; f < 2; f++)
        #pragma unroll
        for (int j = 0; j < 8; j++)
            #pragma unroll
            for (int e = 0; e < 4; e++) acc[f][j][e] = 0.f;

    load_chunk(0);

    const int lrow = lane & 15;
    const int lkof = (lane >> 4) * 16;               // bytes

    for (int c = 0; c < NC; c++) {
        if (c + 1 < NC) {
            load_chunk(c + 1);
            asm volatile("cp.async.wait_group 1;" ::: "memory");
        } else {
            asm volatile("cp.async.wait_group 0;" ::: "memory");
        }
        __syncthreads();
        const uint32_t stg = sb + (c & 1) * STAGE;
        const uint32_t aOff = stg + (warp_m * 32 + lrow) * RSTRIDE + lkof;
        const uint32_t bOff = stg + ((PASSES == 3 ? 2 : 1) * TSZ)
                            + (warp_n * 64 + lrow) * RSTRIDE + lkof;
        #pragma unroll
        for (int ks = 0; ks < 2; ks++) {
            const uint32_t kb = ks * 32;             // 16 elems = 32 bytes
            uint32_t ah[2][4], bh[4][4];
            #pragma unroll
            for (int f = 0; f < 2; f++) LDSM4(ah[f], aOff + f * 16 * RSTRIDE + kb);
            #pragma unroll
            for (int g = 0; g < 4; g++) LDSM4(bh[g], bOff + g * 16 * RSTRIDE + kb);
            if (PASSES == 3) {
                uint32_t al[2][4], bl[4][4];
                #pragma unroll
                for (int f = 0; f < 2; f++) LDSM4(al[f], aOff + TSZ + f * 16 * RSTRIDE + kb);
                #pragma unroll
                for (int g = 0; g < 4; g++) LDSM4(bl[g], bOff + TSZ + g * 16 * RSTRIDE + kb);
                // ---- pass-major order: accumulator reuse distance = 16 MMAs ----
                #pragma unroll
                for (int f = 0; f < 2; f++)
                    #pragma unroll
                    for (int g = 0; g < 4; g++) {
                        MMA_F16_F32(acc[f][2 * g + 0], ah[f], bh[g][0], bh[g][2]);
                        MMA_F16_F32(acc[f][2 * g + 1], ah[f], bh[g][1], bh[g][3]);
                    }
                #pragma unroll
                for (int f = 0; f < 2; f++)
                    #pragma unroll
                    for (int g = 0; g < 4; g++) {
                        MMA_F16_F32(acc[f][2 * g + 0], ah[f], bl[g][0], bl[g][2]);
                        MMA_F16_F32(acc[f][2 * g + 1], ah[f], bl[g][1], bl[g][3]);
                    }
                #pragma unroll
                for (int f = 0; f < 2; f++)
                    #pragma unroll
                    for (int g = 0; g < 4; g++) {
                        MMA_F16_F32(acc[f][2 * g + 0], al[f], bh[g][0], bh[g][2]);
                        MMA_F16_F32(acc[f][2 * g + 1], al[f], bh[g][1], bh[g][3]);
                    }
            } else {
                #pragma unroll
                for (int f = 0; f < 2; f++)
                    #pragma unroll
                    for (int g = 0; g < 4; g++) {
                        MMA_F16_F32(acc[f][2 * g + 0], ah[f], bh[g][0], bh[g][2]);
                        MMA_F16_F32(acc[f][2 * g + 1], ah[f], bh[g][1], bh[g][3]);
                    }
            }
        }
        __syncthreads();
    }

    // ------------------------------- epilogue -------------------------------
    const int qrow = lane >> 2;
    const int qcol = (lane & 3) * 2;
    #pragma unroll
    for (int f = 0; f < 2; f++) {
        const int m0 = bm + warp_m * 32 + f * 16 + qrow;
        #pragma unroll
        for (int j = 0; j < 8; j++) {
            const int n = bn + warp_n * 64 + j * 8 + qcol;
            if (OUTMODE == 0) {
                float* Cf = (float*)Cp + (long long)bz * cStr;
                float2 v0 = make_float2(acc[f][j][0], acc[f][j][1]);
                float2 v1 = make_float2(acc[f][j][2], acc[f][j][3]);
                if (bias) {
                    float2 b0 = *(const float2*)(bias + (long long)m0 * Ng + n);
                    float2 b1 = *(const float2*)(bias + (long long)(m0 + 8) * Ng + n);
                    v0.x += b0.x; v0.y += b0.y; v1.x += b1.x; v1.y += b1.y;
                }
                v0.x *= alpha; v0.y *= alpha; v1.x *= alpha; v1.y *= alpha;
                *(float2*)(Cf + (long long)m0 * Ng + n) = v0;
                *(float2*)(Cf + (long long)(m0 + 8) * Ng + n) = v1;
            } else {
                __half* Cb = (__half*)Cp;
                *(__half2*)(Cb + (long long)m0 * Ng + n) = __floats2half2_rn(acc[f][j][0], acc[f][j][1]);
                *(__half2*)(Cb + (long long)(m0 + 8) * Ng + n) = __floats2half2_rn(acc[f][j][2], acc[f][j][3]);
            }
        }
    }
}

// ----------------- fp32 -> fp16 hi/lo split (4x ILP, coalesced) -------------
template<int WLO>
__global__ __launch_bounds__(256)
void split_k(const float4* __restrict__ src, __half* __restrict__ hi,
             __half* __restrict__ lo, int n4)
{
    const int i0 = blockIdx.x * 1024 + threadIdx.x;   // 4 float4 per thread
    float4 x[4];
    #pragma unroll
    for (int j = 0; j < 4; j++) x[j] = src[i0 + j * 256];
    #pragma unroll
    for (int j = 0; j < 4; j++) {
        const int i = i0 + j * 256;
        __half h0 = __float2half_rn(x[j].x), h1 = __float2half_rn(x[j].y);
        __half h2 = __float2half_rn(x[j].z), h3 = __float2half_rn(x[j].w);
        __half2 H0; H0.x = h0; H0.y = h1;
        __half2 H1; H1.x = h2; H1.y = h3;
        ((__half2*)hi)[2 * i]     = H0;
        ((__half2*)hi)[2 * i + 1] = H1;
        if (WLO) {
            __half2 L0, L1;
            L0.x = __float2half_rn(x[j].x - __half2float(h0));
            L0.y = __float2half_rn(x[j].y - __half2float(h1));
            L1.x = __float2half_rn(x[j].z - __half2float(h2));
            L1.y = __float2half_rn(x[j].w - __half2float(h3));
            ((__half2*)lo)[2 * i]     = L0;
            ((__half2*)lo)[2 * i + 1] = L1;
        }
    }
}

// ------------------- transpose + convert: dst[c][r] = src[r][c] -------------
__global__ __launch_bounds__(256)
void tsplit_k(const float* __restrict__ src, __half* __restrict__ hi,
              int R, int C, long long sStr, long long dStr)
{
    __shared__ float tile[32][33];
    src += (long long)blockIdx.z * sStr;
    const int c0 = blockIdx.x * 32, r0 = blockIdx.y * 32;
    const int tx = threadIdx.x, ty = threadIdx.y;   // block (32,8)
    #pragma unroll
    for (int i = 0; i < 4; i++)
        tile[ty + i * 8][tx] = src[(long long)(r0 + ty + i * 8) * C + c0 + tx];
    __syncthreads();
    #pragma unroll
    for (int i = 0; i < 4; i++) {
        long long o = (long long)blockIdx.z * dStr + (long long)(c0 + ty + i * 8) * R + r0 + tx;
        hi[o] = __float2half_rn(tile[tx][ty + i * 8]);
    }
}

// ------------------------------- softmax ------------------------------------
__global__ __launch_bounds__(256)
void softmax_kernel(const float* __restrict__ scores, float* __restrict__ attn_out,
                    __half* __restrict__ ahi)
{
    const size_t row = blockIdx.x;
    const float* p = scores + row * SEQ;
    const int t = threadIdx.x;
    __shared__ float red[8];

    float v[8];
    float mx = -INFINITY;
    #pragma unroll
    for (int i = 0; i < 8; i++) { v[i] = p[t + i * 256]; mx = fmaxf(mx, v[i]); }
    #pragma unroll
    for (int o = 16; o; o >>= 1) mx = fmaxf(mx, __shfl_xor_sync(0xffffffffu, mx, o));
    if ((t & 31) == 0) red[t >> 5] = mx;
    __syncthreads();
    mx = red[0];
    #pragma unroll
    for (int w = 1; w < 8; w++) mx = fmaxf(mx, red[w]);
    __syncthreads();

    float s = 0.f;
    #pragma unroll
    for (int i = 0; i < 8; i++) { v[i] = __expf(v[i] - mx); s += v[i]; }
    #pragma unroll
    for (int o = 16; o; o >>= 1) s += __shfl_xor_sync(0xffffffffu, s, o);
    if ((t & 31) == 0) red[t >> 5] = s;
    __syncthreads();
    s = 0.f;
    #pragma unroll
    for (int w = 0; w < 8; w++) s += red[w];

    const float inv = 1.f / s;
    #pragma unroll
    for (int i = 0; i < 8; i++) {
        const float a = v[i] * inv;
        const size_t idx = row * SEQ + t + i * 256;
        if (attn_out) attn_out[idx] = a;
        if (ahi) ahi[idx] = __float2half_rn(a);
    }
}

// ---------------------------------------------------------------------------
extern "C" void kernel_launch(void* const* d_in, const int* in_sizes, int n_in,
                              void* d_out, int out_size)
{
    const float* q  = (const float*)d_in[0];
    const float* k  = (const float*)d_in[1];
    const float* v  = (const float*)d_in[2];
    const float* pe = (const float*)d_in[3];
    const float* Uq = (const float*)d_in[4];
    const float* Uk = (const float*)d_in[5];
    float* out = (float*)d_out;

    __half *qhi, *qlo, *khi, *klo, *vthi, *ahi;
    __half *pehi, *uqt, *ukt, *qpe, *kpe;
    float *bias, *scores;
    cudaGetSymbolAddress((void**)&qhi,  g_qhi);   cudaGetSymbolAddress((void**)&qlo,  g_qlo);
    cudaGetSymbolAddress((void**)&khi,  g_khi);   cudaGetSymbolAddress((void**)&klo,  g_klo);
    cudaGetSymbolAddress((void**)&vthi, g_vthi);  cudaGetSymbolAddress((void**)&ahi,  g_ahi);
    cudaGetSymbolAddress((void**)&pehi, g_pehi);
    cudaGetSymbolAddress((void**)&uqt,  g_uqt);   cudaGetSymbolAddress((void**)&ukt,  g_ukt);
    cudaGetSymbolAddress((void**)&qpe,  g_qpe);   cudaGetSymbolAddress((void**)&kpe,  g_kpe);
    cudaGetSymbolAddress((void**)&bias, g_bias);  cudaGetSymbolAddress((void**)&scores, g_scores);

    const float invScale = 1.0f / 11.313708498984761f;  // 1/sqrt(2*64)

    const long long ctxElems  = (long long)NB * SEQ * DM;
    const long long attnElems = (long long)NB * SEQ * SEQ;
    float* ctxOut  = out;
    float* attnOut = nullptr;
    if ((long long)out_size == ctxElems + attnElems) {
        attnOut = out + ctxElems;
    } else if ((long long)out_size == attnElems) {
        attnOut = out; ctxOut = nullptr;
    }

    const int SM3 = 2 * 4 * 128 * 80;   // 81920 B
    const int SM1 = 2 * 2 * 128 * 80;   // 40960 B
    cudaFuncSetAttribute(hgemm<3, 0>, cudaFuncAttributeMaxDynamicSharedMemorySize, SM3);
    cudaFuncSetAttribute(hgemm<1, 0>, cudaFuncAttributeMaxDynamicSharedMemorySize, SM1);
    cudaFuncSetAttribute(hgemm<1, 1>, cudaFuncAttributeMaxDynamicSharedMemorySize, SM1);

    // ---- splits (4x-ILP: grid = n4/1024) ----
    split_k<1><<<(int)(NQ / 4 / 1024), 256>>>((const float4*)q, qhi, qlo, (int)(NQ / 4));
    split_k<1><<<(int)(NQ / 4 / 1024), 256>>>((const float4*)k, khi, klo, (int)(NQ / 4));
    split_k<0><<<(int)(NP / 4 / 1024), 256>>>((const float4*)pe, pehi, nullptr, (int)(NP / 4));
    tsplit_k<<<dim3(DM / 32, DM / 32, 1), dim3(32, 8)>>>(Uq, uqt, DM, DM, 0, 0);
    tsplit_k<<<dim3(DM / 32, DM / 32, 1), dim3(32, 8)>>>(Uk, ukt, DM, DM, 0, 0);
    if (ctxOut)
        tsplit_k<<<dim3(DM / 32, SEQ / 32, NB), dim3(32, 8)>>>(
            v, vthi, SEQ, DM, (long long)SEQ * DM, (long long)SEQ * DM);

    // ---- TUPE bias chain (single-pass fp16) ----
    hgemm<1, 1><<<dim3(DM / 128, SEQ / 128, 1), 256, SM1>>>(
        pehi, nullptr, uqt, nullptr, qpe, nullptr, DM, DM, 0, 0, 0, 1.f);
    hgemm<1, 1><<<dim3(DM / 128, SEQ / 128, 1), 256, SM1>>>(
        pehi, nullptr, ukt, nullptr, kpe, nullptr, DM, DM, 0, 0, 0, 1.f);
    hgemm<1, 0><<<dim3(SEQ / 128, SEQ / 128, 1), 256, SM1>>>(
        qpe, nullptr, kpe, nullptr, bias, nullptr, DM, SEQ, 0, 0, 0, 1.f);

    // ---- scores = (q@k^T + bias) * invScale  (3-pass fp16, pass-major) ----
    hgemm<3, 0><<<dim3(SEQ / 128, SEQ / 128, NB), 256, SM3>>>(
        qhi, qlo, khi, klo, scores, bias, DM, SEQ,
        (long long)SEQ * DM, (long long)SEQ * DM, (long long)SEQ * SEQ, invScale);

    // ---- softmax (emits attn fp32 and/or fp16) ----
    softmax_kernel<<<NB * SEQ, 256>>>(scores, attnOut, ctxOut ? ahi : nullptr);

    // ---- ctx^T = v^T @ attn^T  (single-pass fp16, row-major out == swapaxes) ----
    if (ctxOut)
        hgemm<1, 0><<<dim3(SEQ / 128, DM / 128, NB), 256, SM1>>>(
            vthi, nullptr, ahi, nullptr, ctxOut, nullptr, SEQ, SEQ,
            (long long)SEQ * DM, (long long)SEQ * SEQ, (long long)SEQ * DM, 1.f);
}

// round 12
// speedup vs baseline: 1.1856x; 1.1856x over previous
#include <cuda_runtime.h>
#include <cuda_fp16.h>
#include <math.h>
#include <stdint.h>

#define SEQ 2048
#define DM  1024
#define NB  4

static constexpr size_t NQ  = (size_t)NB * SEQ * DM;    //  8388608
static constexpr size_t NSS = (size_t)NB * SEQ * SEQ;   // 16777216
static constexpr size_t NP  = (size_t)SEQ * DM;         //  2097152
static constexpr size_t NU  = (size_t)DM * DM;          //  1048576

// ---- scratch (static device globals; no allocation) ----
__device__ __half g_qhi[NQ];
__device__ __half g_khi[NQ],  g_klo[NQ];
__device__ __half g_vthi[NQ];
__device__ __half g_ahi[NSS];
__device__ __half g_pehi[NP];
__device__ __half g_uqt[NU],  g_ukt[NU];
__device__ __half g_qpe[NP],  g_kpe[NP];
__device__ float  g_bias[(size_t)SEQ * SEQ];
__device__ float  g_scores[NSS];

// ------------------------------- PTX helpers -------------------------------
__device__ __forceinline__ uint32_t s2u(const void* p) {
    uint32_t a;
    asm("{ .reg .u64 t; cvta.to.shared.u64 t, %1; cvt.u32.u64 %0, t; }"
        : "=r"(a) : "l"(p));
    return a;
}
__device__ __forceinline__ void cpa16(uint32_t dst, const void* src) {
    asm volatile("cp.async.cg.shared.global [%0], [%1], 16;" :: "r"(dst), "l"(src) : "memory");
}
#define LDSM4(r, addr) \
    asm volatile("ldmatrix.sync.aligned.m8n8.x4.shared.b16 {%0,%1,%2,%3}, [%4];" \
        : "=r"((r)[0]), "=r"((r)[1]), "=r"((r)[2]), "=r"((r)[3]) : "r"(addr))
#define MMA_F16_F32(d, a, b0, b1) \
    asm volatile("mma.sync.aligned.m16n8k16.row.col.f32.f16.f16.f32 " \
        "{%0,%1,%2,%3}, {%4,%5,%6,%7}, {%8,%9}, {%0,%1,%2,%3};" \
        : "+f"((d)[0]), "+f"((d)[1]), "+f"((d)[2]), "+f"((d)[3]) \
        : "r"((a)[0]), "r"((a)[1]), "r"((a)[2]), "r"((a)[3]), "r"(b0), "r"(b1))

// ---------------------------------------------------------------------------
// fp16 HMMA GEMM: C[M,N] = alpha * (A @ opB [+ bias])
//   PASSES==2: A @ (Bhi + Blo)^T  (one-sided split; pass-major order)
//   PASSES==1: A @ Bhi^T
//   OUTMODE: 0 = fp32 row-major (+bias, *alpha); 1 = fp16 row-major
//   CTA tile 128x128, BK=32, 256 threads (8 warps, warp tile 32x64),
//   2-stage cp.async pipeline, 80B-padded SMEM rows (conflict-free ldmatrix).
// ---------------------------------------------------------------------------
template<int PASSES, int OUTMODE>
__global__ void __launch_bounds__(256, 1)
hgemm(const __half* __restrict__ A, const __half* __restrict__ Bhi,
      const __half* __restrict__ Blo,
      void* __restrict__ Cp, const float* __restrict__ bias, int Kt, int Ng,
      long long aStr, long long bStr, long long cStr, float alpha)
{
    extern __shared__ __align__(128) char smem[];
    constexpr int RSTRIDE = 80;                     // 32 f16 + 16B pad
    constexpr int TSZ = 128 * RSTRIDE;              // 10240 B per tile
    constexpr int NT  = (PASSES == 2) ? 3 : 2;      // tiles per stage
    constexpr int STAGE = NT * TSZ;

    const uint32_t sb = s2u(smem);
    const int tid = threadIdx.x;
    const int lane = tid & 31;
    const int wid = tid >> 5;
    const int warp_m = wid & 3;                      // 4 warps along M
    const int warp_n = wid >> 2;                     // 2 warps along N
    const int bm = blockIdx.y * 128, bn = blockIdx.x * 128, bz = blockIdx.z;
    const int NC = Kt >> 5;                          // chunks of BK=32

    const __half* Ab  = A   + (long long)bz * aStr;
    const __half* Bhb = Bhi + (long long)bz * bStr;
    const __half* Blb = (PASSES == 2) ? Blo + (long long)bz * bStr : nullptr;

    auto load_chunk = [&](int c) {
        const uint32_t stg = sb + (c & 1) * STAGE;
        const long long kc = (long long)c << 5;
        #pragma unroll
        for (int it = 0; it < NT * 2; it++) {
            const int idx = tid + it * 256;          // NT*512 chunks of 16B
            const int t4  = idx >> 9;                // 0=A, 1=Bhi, 2=Blo
            const int r   = (idx >> 2) & 127;        // row in tile
            const int c16 = idx & 3;                 // 16B chunk in row
            const __half* src = (t4 == 0) ? Ab : ((t4 == 1) ? Bhb : Blb);
            const int rowg = ((t4 == 0) ? bm : bn) + r;
            cpa16(stg + t4 * TSZ + r * RSTRIDE + c16 * 16,
                  src + (long long)rowg * Kt + kc + c16 * 8);
        }
        asm volatile("cp.async.commit_group;" ::: "memory");
    };

    float acc[2][8][4];
    #pragma unroll
    for (int f = 0; f < 2; f++)
        #pragma unroll
        for (int j = 0; j < 8; j++)
            #pragma unroll
            for (int e = 0; e < 4; e++) acc[f][j][e] = 0.f;

    load_chunk(0);

    const int lrow = lane & 15;
    const int lkof = (lane >> 4) * 16;               // bytes

    for (int c = 0; c < NC; c++) {
        if (c + 1 < NC) {
            load_chunk(c + 1);
            asm volatile("cp.async.wait_group 1;" ::: "memory");
        } else {
            asm volatile("cp.async.wait_group 0;" ::: "memory");
        }
        __syncthreads();
        const uint32_t stg = sb + (c & 1) * STAGE;
        const uint32_t aOff = stg + (warp_m * 32 + lrow) * RSTRIDE + lkof;
        const uint32_t bOff = stg + TSZ + (warp_n * 64 + lrow) * RSTRIDE + lkof;
        #pragma unroll
        for (int ks = 0; ks < 2; ks++) {
            const uint32_t kb = ks * 32;             // 16 elems = 32 bytes
            uint32_t ah[2][4], bh[4][4];
            #pragma unroll
            for (int f = 0; f < 2; f++) LDSM4(ah[f], aOff + f * 16 * RSTRIDE + kb);
            #pragma unroll
            for (int g = 0; g < 4; g++) LDSM4(bh[g], bOff + g * 16 * RSTRIDE + kb);
            #pragma unroll
            for (int f = 0; f < 2; f++)
                #pragma unroll
                for (int g = 0; g < 4; g++) {
                    MMA_F16_F32(acc[f][2 * g + 0], ah[f], bh[g][0], bh[g][2]);
                    MMA_F16_F32(acc[f][2 * g + 1], ah[f], bh[g][1], bh[g][3]);
                }
            if (PASSES == 2) {
                uint32_t bl[4][4];
                #pragma unroll
                for (int g = 0; g < 4; g++) LDSM4(bl[g], bOff + TSZ + g * 16 * RSTRIDE + kb);
                #pragma unroll
                for (int f = 0; f < 2; f++)
                    #pragma unroll
                    for (int g = 0; g < 4; g++) {
                        MMA_F16_F32(acc[f][2 * g + 0], ah[f], bl[g][0], bl[g][2]);
                        MMA_F16_F32(acc[f][2 * g + 1], ah[f], bl[g][1], bl[g][3]);
                    }
            }
        }
        __syncthreads();
    }

    // ------------------------------- epilogue -------------------------------
    const int qrow = lane >> 2;
    const int qcol = (lane & 3) * 2;
    #pragma unroll
    for (int f = 0; f < 2; f++) {
        const int m0 = bm + warp_m * 32 + f * 16 + qrow;
        #pragma unroll
        for (int j = 0; j < 8; j++) {
            const int n = bn + warp_n * 64 + j * 8 + qcol;
            if (OUTMODE == 0) {
                float* Cf = (float*)Cp + (long long)bz * cStr;
                float2 v0 = make_float2(acc[f][j][0], acc[f][j][1]);
                float2 v1 = make_float2(acc[f][j][2], acc[f][j][3]);
                if (bias) {
                    float2 b0 = *(const float2*)(bias + (long long)m0 * Ng + n);
                    float2 b1 = *(const float2*)(bias + (long long)(m0 + 8) * Ng + n);
                    v0.x += b0.x; v0.y += b0.y; v1.x += b1.x; v1.y += b1.y;
                }
                v0.x *= alpha; v0.y *= alpha; v1.x *= alpha; v1.y *= alpha;
                *(float2*)(Cf + (long long)m0 * Ng + n) = v0;
                *(float2*)(Cf + (long long)(m0 + 8) * Ng + n) = v1;
            } else {
                __half* Cb = (__half*)Cp;
                *(__half2*)(Cb + (long long)m0 * Ng + n) = __floats2half2_rn(acc[f][j][0], acc[f][j][1]);
                *(__half2*)(Cb + (long long)(m0 + 8) * Ng + n) = __floats2half2_rn(acc[f][j][2], acc[f][j][3]);
            }
        }
    }
}

// ----------------- fp32 -> fp16 hi (/lo) split, 4x ILP ----------------------
template<int WLO>
__global__ __launch_bounds__(256)
void split_k(const float4* __restrict__ src, __half* __restrict__ hi,
             __half* __restrict__ lo, int n4)
{
    const int i0 = blockIdx.x * 1024 + threadIdx.x;   // 4 float4 per thread
    float4 x[4];
    #pragma unroll
    for (int j = 0; j < 4; j++) x[j] = src[i0 + j * 256];
    #pragma unroll
    for (int j = 0; j < 4; j++) {
        const int i = i0 + j * 256;
        __half h0 = __float2half_rn(x[j].x), h1 = __float2half_rn(x[j].y);
        __half h2 = __float2half_rn(x[j].z), h3 = __float2half_rn(x[j].w);
        __half2 H0; H0.x = h0; H0.y = h1;
        __half2 H1; H1.x = h2; H1.y = h3;
        ((__half2*)hi)[2 * i]     = H0;
        ((__half2*)hi)[2 * i + 1] = H1;
        if (WLO) {
            __half2 L0, L1;
            L0.x = __float2half_rn(x[j].x - __half2float(h0));
            L0.y = __float2half_rn(x[j].y - __half2float(h1));
            L1.x = __float2half_rn(x[j].z - __half2float(h2));
            L1.y = __float2half_rn(x[j].w - __half2float(h3));
            ((__half2*)lo)[2 * i]     = L0;
            ((__half2*)lo)[2 * i + 1] = L1;
        }
    }
}

// ------------------- transpose + convert: dst[c][r] = src[r][c] -------------
__global__ __launch_bounds__(256)
void tsplit_k(const float* __restrict__ src, __half* __restrict__ hi,
              int R, int C, long long sStr, long long dStr)
{
    __shared__ float tile[32][33];
    src += (long long)blockIdx.z * sStr;
    const int c0 = blockIdx.x * 32, r0 = blockIdx.y * 32;
    const int tx = threadIdx.x, ty = threadIdx.y;   // block (32,8)
    #pragma unroll
    for (int i = 0; i < 4; i++)
        tile[ty + i * 8][tx] = src[(long long)(r0 + ty + i * 8) * C + c0 + tx];
    __syncthreads();
    #pragma unroll
    for (int i = 0; i < 4; i++) {
        long long o = (long long)blockIdx.z * dStr + (long long)(c0 + ty + i * 8) * R + r0 + tx;
        hi[o] = __float2half_rn(tile[tx][ty + i * 8]);
    }
}

// ------------------------------- softmax ------------------------------------
__global__ __launch_bounds__(256)
void softmax_kernel(const float* __restrict__ scores, float* __restrict__ attn_out,
                    __half* __restrict__ ahi)
{
    const size_t row = blockIdx.x;
    const float* p = scores + row * SEQ;
    const int t = threadIdx.x;
    __shared__ float red[8];

    float v[8];
    float mx = -INFINITY;
    #pragma unroll
    for (int i = 0; i < 8; i++) { v[i] = p[t + i * 256]; mx = fmaxf(mx, v[i]); }
    #pragma unroll
    for (int o = 16; o; o >>= 1) mx = fmaxf(mx, __shfl_xor_sync(0xffffffffu, mx, o));
    if ((t & 31) == 0) red[t >> 5] = mx;
    __syncthreads();
    mx = red[0];
    #pragma unroll
    for (int w = 1; w < 8; w++) mx = fmaxf(mx, red[w]);
    __syncthreads();

    float s = 0.f;
    #pragma unroll
    for (int i = 0; i < 8; i++) { v[i] = __expf(v[i] - mx); s += v[i]; }
    #pragma unroll
    for (int o = 16; o; o >>= 1) s += __shfl_xor_sync(0xffffffffu, s, o);
    if ((t & 31) == 0) red[t >> 5] = s;
    __syncthreads();
    s = 0.f;
    #pragma unroll
    for (int w = 0; w < 8; w++) s += red[w];

    const float inv = 1.f / s;
    #pragma unroll
    for (int i = 0; i < 8; i++) {
        const float a = v[i] * inv;
        const size_t idx = row * SEQ + t + i * 256;
        if (attn_out) attn_out[idx] = a;
        if (ahi) ahi[idx] = __float2half_rn(a);
    }
}

// ---------------------------------------------------------------------------
extern "C" void kernel_launch(void* const* d_in, const int* in_sizes, int n_in,
                              void* d_out, int out_size)
{
    const float* q  = (const float*)d_in[0];
    const float* k  = (const float*)d_in[1];
    const float* v  = (const float*)d_in[2];
    const float* pe = (const float*)d_in[3];
    const float* Uq = (const float*)d_in[4];
    const float* Uk = (const float*)d_in[5];
    float* out = (float*)d_out;

    __half *qhi, *khi, *klo, *vthi, *ahi;
    __half *pehi, *uqt, *ukt, *qpe, *kpe;
    float *bias, *scores;
    cudaGetSymbolAddress((void**)&qhi,  g_qhi);
    cudaGetSymbolAddress((void**)&khi,  g_khi);   cudaGetSymbolAddress((void**)&klo,  g_klo);
    cudaGetSymbolAddress((void**)&vthi, g_vthi);  cudaGetSymbolAddress((void**)&ahi,  g_ahi);
    cudaGetSymbolAddress((void**)&pehi, g_pehi);
    cudaGetSymbolAddress((void**)&uqt,  g_uqt);   cudaGetSymbolAddress((void**)&ukt,  g_ukt);
    cudaGetSymbolAddress((void**)&qpe,  g_qpe);   cudaGetSymbolAddress((void**)&kpe,  g_kpe);
    cudaGetSymbolAddress((void**)&bias, g_bias);  cudaGetSymbolAddress((void**)&scores, g_scores);

    const float invScale = 1.0f / 11.313708498984761f;  // 1/sqrt(2*64)

    const long long ctxElems  = (long long)NB * SEQ * DM;
    const long long attnElems = (long long)NB * SEQ * SEQ;
    float* ctxOut  = out;
    float* attnOut = nullptr;
    if ((long long)out_size == ctxElems + attnElems) {
        attnOut = out + ctxElems;
    } else if ((long long)out_size == attnElems) {
        attnOut = out; ctxOut = nullptr;
    }

    const int SM2 = 2 * 3 * 128 * 80;   // 61440 B (2 stages x 3 tiles)
    const int SM1 = 2 * 2 * 128 * 80;   // 40960 B
    cudaFuncSetAttribute(hgemm<2, 0>, cudaFuncAttributeMaxDynamicSharedMemorySize, SM2);
    cudaFuncSetAttribute(hgemm<1, 0>, cudaFuncAttributeMaxDynamicSharedMemorySize, SM1);
    cudaFuncSetAttribute(hgemm<1, 1>, cudaFuncAttributeMaxDynamicSharedMemorySize, SM1);

    // ---- splits (4x-ILP: grid = n4/1024) ----
    split_k<0><<<(int)(NQ / 4 / 1024), 256>>>((const float4*)q, qhi, nullptr, (int)(NQ / 4));
    split_k<1><<<(int)(NQ / 4 / 1024), 256>>>((const float4*)k, khi, klo, (int)(NQ / 4));
    split_k<0><<<(int)(NP / 4 / 1024), 256>>>((const float4*)pe, pehi, nullptr, (int)(NP / 4));
    tsplit_k<<<dim3(DM / 32, DM / 32, 1), dim3(32, 8)>>>(Uq, uqt, DM, DM, 0, 0);
    tsplit_k<<<dim3(DM / 32, DM / 32, 1), dim3(32, 8)>>>(Uk, ukt, DM, DM, 0, 0);
    if (ctxOut)
        tsplit_k<<<dim3(DM / 32, SEQ / 32, NB), dim3(32, 8)>>>(
            v, vthi, SEQ, DM, (long long)SEQ * DM, (long long)SEQ * DM);

    // ---- TUPE bias chain (single-pass fp16) ----
    hgemm<1, 1><<<dim3(DM / 128, SEQ / 128, 1), 256, SM1>>>(
        pehi, uqt, nullptr, qpe, nullptr, DM, DM, 0, 0, 0, 1.f);
    hgemm<1, 1><<<dim3(DM / 128, SEQ / 128, 1), 256, SM1>>>(
        pehi, ukt, nullptr, kpe, nullptr, DM, DM, 0, 0, 0, 1.f);
    hgemm<1, 0><<<dim3(SEQ / 128, SEQ / 128, 1), 256, SM1>>>(
        qpe, kpe, nullptr, bias, nullptr, DM, SEQ, 0, 0, 0, 1.f);

    // ---- scores = (q @ (khi+klo)^T + bias) * invScale  (2-pass fp16) ----
    hgemm<2, 0><<<dim3(SEQ / 128, SEQ / 128, NB), 256, SM2>>>(
        qhi, khi, klo, scores, bias, DM, SEQ,
        (long long)SEQ * DM, (long long)SEQ * DM, (long long)SEQ * SEQ, invScale);

    // ---- softmax (emits attn fp32 and/or fp16) ----
    softmax_kernel<<<NB * SEQ, 256>>>(scores, attnOut, ctxOut ? ahi : nullptr);

    // ---- ctx^T = v^T @ attn^T  (single-pass fp16, row-major out == swapaxes) ----
    if (ctxOut)
        hgemm<1, 0><<<dim3(SEQ / 128, DM / 128, NB), 256, SM1>>>(
            vthi, ahi, nullptr, ctxOut, nullptr, SEQ, SEQ,
            (long long)SEQ * DM, (long long)SEQ * SEQ, (long long)SEQ * DM, 1.f);
}

// round 13
// speedup vs baseline: 1.3925x; 1.1746x over previous
#include <cuda_runtime.h>
#include <cuda_fp16.h>
#include <math.h>
#include <stdint.h>

#define SEQ 2048
#define DM  1024
#define NB  4

static constexpr size_t NQ  = (size_t)NB * SEQ * DM;    //  8388608
static constexpr size_t NSS = (size_t)NB * SEQ * SEQ;   // 16777216
static constexpr size_t NP  = (size_t)SEQ * DM;         //  2097152
static constexpr size_t NU  = (size_t)DM * DM;          //  1048576

// ---- scratch (static device globals; no allocation) ----
__device__ __half g_qhi[NQ];
__device__ __half g_khi[NQ];
__device__ __half g_vthi[NQ];
__device__ __half g_ahi[NSS];
__device__ __half g_pehi[NP];
__device__ __half g_uqt[NU],  g_ukt[NU];
__device__ __half g_qpe[NP],  g_kpe[NP];
__device__ float  g_bias[(size_t)SEQ * SEQ];
__device__ float  g_scores[NSS];

// ------------------------------- PTX helpers -------------------------------
__device__ __forceinline__ uint32_t s2u(const void* p) {
    uint32_t a;
    asm("{ .reg .u64 t; cvta.to.shared.u64 t, %1; cvt.u32.u64 %0, t; }"
        : "=r"(a) : "l"(p));
    return a;
}
__device__ __forceinline__ void cpa16(uint32_t dst, const void* src) {
    asm volatile("cp.async.cg.shared.global [%0], [%1], 16;" :: "r"(dst), "l"(src) : "memory");
}
#define LDSM4(r, addr) \
    asm volatile("ldmatrix.sync.aligned.m8n8.x4.shared.b16 {%0,%1,%2,%3}, [%4];" \
        : "=r"((r)[0]), "=r"((r)[1]), "=r"((r)[2]), "=r"((r)[3]) : "r"(addr))
#define MMA_F16_F32(d, a, b0, b1) \
    asm volatile("mma.sync.aligned.m16n8k16.row.col.f32.f16.f16.f32 " \
        "{%0,%1,%2,%3}, {%4,%5,%6,%7}, {%8,%9}, {%0,%1,%2,%3};" \
        : "+f"((d)[0]), "+f"((d)[1]), "+f"((d)[2]), "+f"((d)[3]) \
        : "r"((a)[0]), "r"((a)[1]), "r"((a)[2]), "r"((a)[3]), "r"(b0), "r"(b1))

// ---------------------------------------------------------------------------
// fp16 HMMA GEMM: C[M,N] = alpha * (A @ opB [+ bias])
//   PASSES==2: A @ (Bhi + Blo)^T  (one-sided split)    PASSES==1: A @ Bhi^T
//   OUTMODE: 0 = fp32 row-major (+bias, *alpha); 1 = fp16 row-major
//   CTA tile 128x128, BK=32, 256 threads (8 warps, warp tile 32x64),
//   2-stage cp.async pipeline, 80B-padded SMEM rows (conflict-free ldmatrix).
// ---------------------------------------------------------------------------
template<int PASSES, int OUTMODE>
__global__ void __launch_bounds__(256, 1)
hgemm(const __half* __restrict__ A, const __half* __restrict__ Bhi,
      const __half* __restrict__ Blo,
      void* __restrict__ Cp, const float* __restrict__ bias, int Kt, int Ng,
      long long aStr, long long bStr, long long cStr, float alpha)
{
    extern __shared__ __align__(128) char smem[];
    constexpr int RSTRIDE = 80;                     // 32 f16 + 16B pad
    constexpr int TSZ = 128 * RSTRIDE;              // 10240 B per tile
    constexpr int NT  = (PASSES == 2) ? 3 : 2;      // tiles per stage
    constexpr int STAGE = NT * TSZ;

    const uint32_t sb = s2u(smem);
    const int tid = threadIdx.x;
    const int lane = tid & 31;
    const int wid = tid >> 5;
    const int warp_m = wid & 3;                      // 4 warps along M
    const int warp_n = wid >> 2;                     // 2 warps along N
    const int bm = blockIdx.y * 128, bn = blockIdx.x * 128, bz = blockIdx.z;
    const int NC = Kt >> 5;                          // chunks of BK=32

    const __half* Ab  = A   + (long long)bz * aStr;
    const __half* Bhb = Bhi + (long long)bz * bStr;
    const __half* Blb = (PASSES == 2) ? Blo + (long long)bz * bStr : nullptr;

    auto load_chunk = [&](int c) {
        const uint32_t stg = sb + (c & 1) * STAGE;
        const long long kc = (long long)c << 5;
        #pragma unroll
        for (int it = 0; it < NT * 2; it++) {
            const int idx = tid + it * 256;          // NT*512 chunks of 16B
            const int t4  = idx >> 9;                // 0=A, 1=Bhi, 2=Blo
            const int r   = (idx >> 2) & 127;        // row in tile
            const int c16 = idx & 3;                 // 16B chunk in row
            const __half* src = (t4 == 0) ? Ab : ((t4 == 1) ? Bhb : Blb);
            const int rowg = ((t4 == 0) ? bm : bn) + r;
            cpa16(stg + t4 * TSZ + r * RSTRIDE + c16 * 16,
                  src + (long long)rowg * Kt + kc + c16 * 8);
        }
        asm volatile("cp.async.commit_group;" ::: "memory");
    };

    float acc[2][8][4];
    #pragma unroll
    for (int f = 0; f < 2; f++)
        #pragma unroll
        for (int j = 0; j < 8; j++)
            #pragma unroll
            for (int e = 0; e < 4; e++) acc[f][j][e] = 0.f;

    load_chunk(0);

    const int lrow = lane & 15;
    const int lkof = (lane >> 4) * 16;               // bytes

    for (int c = 0; c < NC; c++) {
        if (c + 1 < NC) {
            load_chunk(c + 1);
            asm volatile("cp.async.wait_group 1;" ::: "memory");
        } else {
            asm volatile("cp.async.wait_group 0;" ::: "memory");
        }
        __syncthreads();
        const uint32_t stg = sb + (c & 1) * STAGE;
        const uint32_t aOff = stg + (warp_m * 32 + lrow) * RSTRIDE + lkof;
        const uint32_t bOff = stg + TSZ + (warp_n * 64 + lrow) * RSTRIDE + lkof;
        #pragma unroll
        for (int ks = 0; ks < 2; ks++) {
            const uint32_t kb = ks * 32;             // 16 elems = 32 bytes
            uint32_t ah[2][4], bh[4][4];
            #pragma unroll
            for (int f = 0; f < 2; f++) LDSM4(ah[f], aOff + f * 16 * RSTRIDE + kb);
            #pragma unroll
            for (int g = 0; g < 4; g++) LDSM4(bh[g], bOff + g * 16 * RSTRIDE + kb);
            #pragma unroll
            for (int f = 0; f < 2; f++)
                #pragma unroll
                for (int g = 0; g < 4; g++) {
                    MMA_F16_F32(acc[f][2 * g + 0], ah[f], bh[g][0], bh[g][2]);
                    MMA_F16_F32(acc[f][2 * g + 1], ah[f], bh[g][1], bh[g][3]);
                }
            if (PASSES == 2) {
                uint32_t bl[4][4];
                #pragma unroll
                for (int g = 0; g < 4; g++) LDSM4(bl[g], bOff + TSZ + g * 16 * RSTRIDE + kb);
                #pragma unroll
                for (int f = 0; f < 2; f++)
                    #pragma unroll
                    for (int g = 0; g < 4; g++) {
                        MMA_F16_F32(acc[f][2 * g + 0], ah[f], bl[g][0], bl[g][2]);
                        MMA_F16_F32(acc[f][2 * g + 1], ah[f], bl[g][1], bl[g][3]);
                    }
            }
        }
        __syncthreads();
    }

    // ------------------------------- epilogue -------------------------------
    const int qrow = lane >> 2;
    const int qcol = (lane & 3) * 2;
    #pragma unroll
    for (int f = 0; f < 2; f++) {
        const int m0 = bm + warp_m * 32 + f * 16 + qrow;
        #pragma unroll
        for (int j = 0; j < 8; j++) {
            const int n = bn + warp_n * 64 + j * 8 + qcol;
            if (OUTMODE == 0) {
                float* Cf = (float*)Cp + (long long)bz * cStr;
                float2 v0 = make_float2(acc[f][j][0], acc[f][j][1]);
                float2 v1 = make_float2(acc[f][j][2], acc[f][j][3]);
                if (bias) {
                    float2 b0 = *(const float2*)(bias + (long long)m0 * Ng + n);
                    float2 b1 = *(const float2*)(bias + (long long)(m0 + 8) * Ng + n);
                    v0.x += b0.x; v0.y += b0.y; v1.x += b1.x; v1.y += b1.y;
                }
                v0.x *= alpha; v0.y *= alpha; v1.x *= alpha; v1.y *= alpha;
                *(float2*)(Cf + (long long)m0 * Ng + n) = v0;
                *(float2*)(Cf + (long long)(m0 + 8) * Ng + n) = v1;
            } else {
                __half* Cb = (__half*)Cp;
                *(__half2*)(Cb + (long long)m0 * Ng + n) = __floats2half2_rn(acc[f][j][0], acc[f][j][1]);
                *(__half2*)(Cb + (long long)(m0 + 8) * Ng + n) = __floats2half2_rn(acc[f][j][2], acc[f][j][3]);
            }
        }
    }
}

// ----------------- fp32 -> fp16 convert, 4x ILP -----------------------------
__global__ __launch_bounds__(256)
void split_k(const float4* __restrict__ src, __half* __restrict__ hi, int n4)
{
    const int i0 = blockIdx.x * 1024 + threadIdx.x;   // 4 float4 per thread
    float4 x[4];
    #pragma unroll
    for (int j = 0; j < 4; j++) x[j] = src[i0 + j * 256];
    #pragma unroll
    for (int j = 0; j < 4; j++) {
        const int i = i0 + j * 256;
        ((__half2*)hi)[2 * i]     = __floats2half2_rn(x[j].x, x[j].y);
        ((__half2*)hi)[2 * i + 1] = __floats2half2_rn(x[j].z, x[j].w);
    }
}

// ------------------- transpose + convert: dst[c][r] = src[r][c] -------------
__global__ __launch_bounds__(256)
void tsplit_k(const float* __restrict__ src, __half* __restrict__ hi,
              int R, int C, long long sStr, long long dStr)
{
    __shared__ float tile[32][33];
    src += (long long)blockIdx.z * sStr;
    const int c0 = blockIdx.x * 32, r0 = blockIdx.y * 32;
    const int tx = threadIdx.x, ty = threadIdx.y;   // block (32,8)
    #pragma unroll
    for (int i = 0; i < 4; i++)
        tile[ty + i * 8][tx] = src[(long long)(r0 + ty + i * 8) * C + c0 + tx];
    __syncthreads();
    #pragma unroll
    for (int i = 0; i < 4; i++) {
        long long o = (long long)blockIdx.z * dStr + (long long)(c0 + ty + i * 8) * R + r0 + tx;
        hi[o] = __float2half_rn(tile[tx][ty + i * 8]);
    }
}

// ------------------------------- softmax ------------------------------------
__global__ __launch_bounds__(256)
void softmax_kernel(const float* __restrict__ scores, float* __restrict__ attn_out,
                    __half* __restrict__ ahi)
{
    const size_t row = blockIdx.x;
    const float* p = scores + row * SEQ;
    const int t = threadIdx.x;
    __shared__ float red[8];

    float v[8];
    float mx = -INFINITY;
    #pragma unroll
    for (int i = 0; i < 8; i++) { v[i] = p[t + i * 256]; mx = fmaxf(mx, v[i]); }
    #pragma unroll
    for (int o = 16; o; o >>= 1) mx = fmaxf(mx, __shfl_xor_sync(0xffffffffu, mx, o));
    if ((t & 31) == 0) red[t >> 5] = mx;
    __syncthreads();
    mx = red[0];
    #pragma unroll
    for (int w = 1; w < 8; w++) mx = fmaxf(mx, red[w]);
    __syncthreads();

    float s = 0.f;
    #pragma unroll
    for (int i = 0; i < 8; i++) { v[i] = __expf(v[i] - mx); s += v[i]; }
    #pragma unroll
    for (int o = 16; o; o >>= 1) s += __shfl_xor_sync(0xffffffffu, s, o);
    if ((t & 31) == 0) red[t >> 5] = s;
    __syncthreads();
    s = 0.f;
    #pragma unroll
    for (int w = 0; w < 8; w++) s += red[w];

    const float inv = 1.f / s;
    #pragma unroll
    for (int i = 0; i < 8; i++) {
        const float a = v[i] * inv;
        const size_t idx = row * SEQ + t + i * 256;
        if (attn_out) attn_out[idx] = a;
        if (ahi) ahi[idx] = __float2half_rn(a);
    }
}

// ---------------------------------------------------------------------------
extern "C" void kernel_launch(void* const* d_in, const int* in_sizes, int n_in,
                              void* d_out, int out_size)
{
    const float* q  = (const float*)d_in[0];
    const float* k  = (const float*)d_in[1];
    const float* v  = (const float*)d_in[2];
    const float* pe = (const float*)d_in[3];
    const float* Uq = (const float*)d_in[4];
    const float* Uk = (const float*)d_in[5];
    float* out = (float*)d_out;

    __half *qhi, *khi, *vthi, *ahi;
    __half *pehi, *uqt, *ukt, *qpe, *kpe;
    float *bias, *scores;
    cudaGetSymbolAddress((void**)&qhi,  g_qhi);
    cudaGetSymbolAddress((void**)&khi,  g_khi);
    cudaGetSymbolAddress((void**)&vthi, g_vthi);  cudaGetSymbolAddress((void**)&ahi,  g_ahi);
    cudaGetSymbolAddress((void**)&pehi, g_pehi);
    cudaGetSymbolAddress((void**)&uqt,  g_uqt);   cudaGetSymbolAddress((void**)&ukt,  g_ukt);
    cudaGetSymbolAddress((void**)&qpe,  g_qpe);   cudaGetSymbolAddress((void**)&kpe,  g_kpe);
    cudaGetSymbolAddress((void**)&bias, g_bias);  cudaGetSymbolAddress((void**)&scores, g_scores);

    const float invScale = 1.0f / 11.313708498984761f;  // 1/sqrt(2*64)

    const long long ctxElems  = (long long)NB * SEQ * DM;
    const long long attnElems = (long long)NB * SEQ * SEQ;
    float* ctxOut  = out;
    float* attnOut = nullptr;
    if ((long long)out_size == ctxElems + attnElems) {
        attnOut = out + ctxElems;
    } else if ((long long)out_size == attnElems) {
        attnOut = out; ctxOut = nullptr;
    }

    const int SM1 = 2 * 2 * 128 * 80;   // 40960 B (2 stages x 2 tiles)
    cudaFuncSetAttribute(hgemm<1, 0>, cudaFuncAttributeMaxDynamicSharedMemorySize, SM1);
    cudaFuncSetAttribute(hgemm<1, 1>, cudaFuncAttributeMaxDynamicSharedMemorySize, SM1);

    // ---- converts (4x-ILP: grid = n4/1024) ----
    split_k<<<(int)(NQ / 4 / 1024), 256>>>((const float4*)q, qhi, (int)(NQ / 4));
    split_k<<<(int)(NQ / 4 / 1024), 256>>>((const float4*)k, khi, (int)(NQ / 4));
    split_k<<<(int)(NP / 4 / 1024), 256>>>((const float4*)pe, pehi, (int)(NP / 4));
    tsplit_k<<<dim3(DM / 32, DM / 32, 1), dim3(32, 8)>>>(Uq, uqt, DM, DM, 0, 0);
    tsplit_k<<<dim3(DM / 32, DM / 32, 1), dim3(32, 8)>>>(Uk, ukt, DM, DM, 0, 0);
    if (ctxOut)
        tsplit_k<<<dim3(DM / 32, SEQ / 32, NB), dim3(32, 8)>>>(
            v, vthi, SEQ, DM, (long long)SEQ * DM, (long long)SEQ * DM);

    // ---- TUPE bias chain (single-pass fp16) ----
    hgemm<1, 1><<<dim3(DM / 128, SEQ / 128, 1), 256, SM1>>>(
        pehi, uqt, nullptr, qpe, nullptr, DM, DM, 0, 0, 0, 1.f);
    hgemm<1, 1><<<dim3(DM / 128, SEQ / 128, 1), 256, SM1>>>(
        pehi, ukt, nullptr, kpe, nullptr, DM, DM, 0, 0, 0, 1.f);
    hgemm<1, 0><<<dim3(SEQ / 128, SEQ / 128, 1), 256, SM1>>>(
        qpe, kpe, nullptr, bias, nullptr, DM, SEQ, 0, 0, 0, 1.f);

    // ---- scores = (q @ k^T + bias) * invScale  (single-pass fp16) ----
    hgemm<1, 0><<<dim3(SEQ / 128, SEQ / 128, NB), 256, SM1>>>(
        qhi, khi, nullptr, scores, bias, DM, SEQ,
        (long long)SEQ * DM, (long long)SEQ * DM, (long long)SEQ * SEQ, invScale);

    // ---- softmax (emits attn fp32 and/or fp16) ----
    softmax_kernel<<<NB * SEQ, 256>>>(scores, attnOut, ctxOut ? ahi : nullptr);

    // ---- ctx^T = v^T @ attn^T  (single-pass fp16, row-major out == swapaxes) ----
    if (ctxOut)
        hgemm<1, 0><<<dim3(SEQ / 128, DM / 128, NB), 256, SM1>>>(
            vthi, ahi, nullptr, ctxOut, nullptr, SEQ, SEQ,
            (long long)SEQ * DM, (long long)SEQ * SEQ, (long long)SEQ * DM, 1.f);
}

// round 14
// speedup vs baseline: 1.6122x; 1.1578x over previous
#include <cuda_runtime.h>
#include <cuda_fp16.h>
#include <math.h>
#include <stdint.h>

#define SEQ 2048
#define DM  1024
#define NB  4

static constexpr size_t NQ  = (size_t)NB * SEQ * DM;    //  8388608
static constexpr size_t NSS = (size_t)NB * SEQ * SEQ;   // 16777216
static constexpr size_t NP  = (size_t)SEQ * DM;         //  2097152
static constexpr size_t NU  = (size_t)DM * DM;          //  1048576

// ---- scratch (static device globals; no allocation) ----
__device__ __half g_qhi[NQ];
__device__ __half g_khi[NQ];
__device__ __half g_vthi[NQ];
__device__ __half g_ahi[NSS];
__device__ __half g_pehi[NP];
__device__ __half g_uqt[NU],  g_ukt[NU];
__device__ __half g_qpe[NP],  g_kpe[NP];
__device__ float  g_bias[(size_t)SEQ * SEQ];
__device__ float  g_scores[NSS];

// ------------------------------- PTX helpers -------------------------------
__device__ __forceinline__ uint32_t s2u(const void* p) {
    uint32_t a;
    asm("{ .reg .u64 t; cvta.to.shared.u64 t, %1; cvt.u32.u64 %0, t; }"
        : "=r"(a) : "l"(p));
    return a;
}
__device__ __forceinline__ void cpa16(uint32_t dst, const void* src) {
    asm volatile("cp.async.cg.shared.global [%0], [%1], 16;" :: "r"(dst), "l"(src) : "memory");
}
#define LDSM4(r, addr) \
    asm volatile("ldmatrix.sync.aligned.m8n8.x4.shared.b16 {%0,%1,%2,%3}, [%4];" \
        : "=r"((r)[0]), "=r"((r)[1]), "=r"((r)[2]), "=r"((r)[3]) : "r"(addr))
#define MMA_F16_F32(d, a, b0, b1) \
    asm volatile("mma.sync.aligned.m16n8k16.row.col.f32.f16.f16.f32 " \
        "{%0,%1,%2,%3}, {%4,%5,%6,%7}, {%8,%9}, {%0,%1,%2,%3};" \
        : "+f"((d)[0]), "+f"((d)[1]), "+f"((d)[2]), "+f"((d)[3]) \
        : "r"((a)[0]), "r"((a)[1]), "r"((a)[2]), "r"((a)[3]), "r"(b0), "r"(b1))

// ---------------------------------------------------------------------------
// fp16 HMMA GEMM (single pass): C[M,N] = alpha * (A @ B^T [+ bias])
//   OUTMODE: 0 = fp32 row-major (+bias, *alpha); 1 = fp16 row-major
//   CTA tile 128x128, BK=32, 256 threads (8 warps, warp tile 32x64),
//   2-stage cp.async pipeline, 80B-padded SMEM rows (conflict-free ldmatrix),
//   2 CTAs/SM (40KB SMEM each) to test warp-interleave HMMA throughput.
// ---------------------------------------------------------------------------
template<int OUTMODE>
__global__ void __launch_bounds__(256, 2)
hgemm(const __half* __restrict__ A, const __half* __restrict__ B,
      void* __restrict__ Cp, const float* __restrict__ bias, int Kt, int Ng,
      long long aStr, long long bStr, long long cStr, float alpha)
{
    extern __shared__ __align__(128) char smem[];
    constexpr int RSTRIDE = 80;                     // 32 f16 + 16B pad
    constexpr int TSZ = 128 * RSTRIDE;              // 10240 B per tile
    constexpr int STAGE = 2 * TSZ;

    const uint32_t sb = s2u(smem);
    const int tid = threadIdx.x;
    const int lane = tid & 31;
    const int wid = tid >> 5;
    const int warp_m = wid & 3;                      // 4 warps along M
    const int warp_n = wid >> 2;                     // 2 warps along N
    const int bm = blockIdx.y * 128, bn = blockIdx.x * 128, bz = blockIdx.z;
    const int NC = Kt >> 5;                          // chunks of BK=32

    const __half* Ab = A + (long long)bz * aStr;
    const __half* Bb = B + (long long)bz * bStr;

    auto load_chunk = [&](int c) {
        const uint32_t stg = sb + (c & 1) * STAGE;
        const long long kc = (long long)c << 5;
        #pragma unroll
        for (int it = 0; it < 4; it++) {
            const int idx = tid + it * 256;          // 1024 chunks of 16B
            const int t4  = idx >> 9;                // 0=A, 1=B
            const int r   = (idx >> 2) & 127;        // row in tile
            const int c16 = idx & 3;                 // 16B chunk in row
            const __half* src = t4 ? Bb : Ab;
            const int rowg = (t4 ? bn : bm) + r;
            cpa16(stg + t4 * TSZ + r * RSTRIDE + c16 * 16,
                  src + (long long)rowg * Kt + kc + c16 * 8);
        }
        asm volatile("cp.async.commit_group;" ::: "memory");
    };

    float acc[2][8][4];
    #pragma unroll
    for (int f = 0; f < 2; f++)
        #pragma unroll
        for (int j = 0; j < 8; j++)
            #pragma unroll
            for (int e = 0; e < 4; e++) acc[f][j][e] = 0.f;

    load_chunk(0);

    const int lrow = lane & 15;
    const int lkof = (lane >> 4) * 16;               // bytes

    for (int c = 0; c < NC; c++) {
        if (c + 1 < NC) {
            load_chunk(c + 1);
            asm volatile("cp.async.wait_group 1;" ::: "memory");
        } else {
            asm volatile("cp.async.wait_group 0;" ::: "memory");
        }
        __syncthreads();
        const uint32_t stg = sb + (c & 1) * STAGE;
        const uint32_t aOff = stg + (warp_m * 32 + lrow) * RSTRIDE + lkof;
        const uint32_t bOff = stg + TSZ + (warp_n * 64 + lrow) * RSTRIDE + lkof;
        #pragma unroll
        for (int ks = 0; ks < 2; ks++) {
            const uint32_t kb = ks * 32;             // 16 elems = 32 bytes
            uint32_t ah[2][4], bh[4][4];
            #pragma unroll
            for (int f = 0; f < 2; f++) LDSM4(ah[f], aOff + f * 16 * RSTRIDE + kb);
            #pragma unroll
            for (int g = 0; g < 4; g++) LDSM4(bh[g], bOff + g * 16 * RSTRIDE + kb);
            #pragma unroll
            for (int f = 0; f < 2; f++)
                #pragma unroll
                for (int g = 0; g < 4; g++) {
                    MMA_F16_F32(acc[f][2 * g + 0], ah[f], bh[g][0], bh[g][2]);
                    MMA_F16_F32(acc[f][2 * g + 1], ah[f], bh[g][1], bh[g][3]);
                }
        }
        __syncthreads();
    }

    // ------------------------------- epilogue -------------------------------
    const int qrow = lane >> 2;
    const int qcol = (lane & 3) * 2;
    #pragma unroll
    for (int f = 0; f < 2; f++) {
        const int m0 = bm + warp_m * 32 + f * 16 + qrow;
        #pragma unroll
        for (int j = 0; j < 8; j++) {
            const int n = bn + warp_n * 64 + j * 8 + qcol;
            if (OUTMODE == 0) {
                float* Cf = (float*)Cp + (long long)bz * cStr;
                float2 v0 = make_float2(acc[f][j][0], acc[f][j][1]);
                float2 v1 = make_float2(acc[f][j][2], acc[f][j][3]);
                if (bias) {
                    float2 b0 = *(const float2*)(bias + (long long)m0 * Ng + n);
                    float2 b1 = *(const float2*)(bias + (long long)(m0 + 8) * Ng + n);
                    v0.x += b0.x; v0.y += b0.y; v1.x += b1.x; v1.y += b1.y;
                }
                v0.x *= alpha; v0.y *= alpha; v1.x *= alpha; v1.y *= alpha;
                *(float2*)(Cf + (long long)m0 * Ng + n) = v0;
                *(float2*)(Cf + (long long)(m0 + 8) * Ng + n) = v1;
            } else {
                __half* Cb = (__half*)Cp;
                *(__half2*)(Cb + (long long)m0 * Ng + n) = __floats2half2_rn(acc[f][j][0], acc[f][j][1]);
                *(__half2*)(Cb + (long long)(m0 + 8) * Ng + n) = __floats2half2_rn(acc[f][j][2], acc[f][j][3]);
            }
        }
    }
}

// ----------------- fp32 -> fp16 convert, 4x ILP -----------------------------
__global__ __launch_bounds__(256)
void split_k(const float4* __restrict__ src, __half* __restrict__ hi, int n4)
{
    const int i0 = blockIdx.x * 1024 + threadIdx.x;   // 4 float4 per thread
    float4 x[4];
    #pragma unroll
    for (int j = 0; j < 4; j++) x[j] = src[i0 + j * 256];
    #pragma unroll
    for (int j = 0; j < 4; j++) {
        const int i = i0 + j * 256;
        ((__half2*)hi)[2 * i]     = __floats2half2_rn(x[j].x, x[j].y);
        ((__half2*)hi)[2 * i + 1] = __floats2half2_rn(x[j].z, x[j].w);
    }
}

// ------------------- transpose + convert: dst[c][r] = src[r][c] -------------
__global__ __launch_bounds__(256)
void tsplit_k(const float* __restrict__ src, __half* __restrict__ hi,
              int R, int C, long long sStr, long long dStr)
{
    __shared__ float tile[32][33];
    src += (long long)blockIdx.z * sStr;
    const int c0 = blockIdx.x * 32, r0 = blockIdx.y * 32;
    const int tx = threadIdx.x, ty = threadIdx.y;   // block (32,8)
    #pragma unroll
    for (int i = 0; i < 4; i++)
        tile[ty + i * 8][tx] = src[(long long)(r0 + ty + i * 8) * C + c0 + tx];
    __syncthreads();
    #pragma unroll
    for (int i = 0; i < 4; i++) {
        long long o = (long long)blockIdx.z * dStr + (long long)(c0 + ty + i * 8) * R + r0 + tx;
        hi[o] = __float2half_rn(tile[tx][ty + i * 8]);
    }
}

// ------------------------------- softmax ------------------------------------
__global__ __launch_bounds__(256)
void softmax_kernel(const float* __restrict__ scores, float* __restrict__ attn_out,
                    __half* __restrict__ ahi)
{
    const size_t row = blockIdx.x;
    const float* p = scores + row * SEQ;
    const int t = threadIdx.x;
    __shared__ float red[8];

    float v[8];
    float mx = -INFINITY;
    #pragma unroll
    for (int i = 0; i < 8; i++) { v[i] = p[t + i * 256]; mx = fmaxf(mx, v[i]); }
    #pragma unroll
    for (int o = 16; o; o >>= 1) mx = fmaxf(mx, __shfl_xor_sync(0xffffffffu, mx, o));
    if ((t & 31) == 0) red[t >> 5] = mx;
    __syncthreads();
    mx = red[0];
    #pragma unroll
    for (int w = 1; w < 8; w++) mx = fmaxf(mx, red[w]);
    __syncthreads();

    float s = 0.f;
    #pragma unroll
    for (int i = 0; i < 8; i++) { v[i] = __expf(v[i] - mx); s += v[i]; }
    #pragma unroll
    for (int o = 16; o; o >>= 1) s += __shfl_xor_sync(0xffffffffu, s, o);
    if ((t & 31) == 0) red[t >> 5] = s;
    __syncthreads();
    s = 0.f;
    #pragma unroll
    for (int w = 0; w < 8; w++) s += red[w];

    const float inv = 1.f / s;
    #pragma unroll
    for (int i = 0; i < 8; i++) {
        const float a = v[i] * inv;
        const size_t idx = row * SEQ + t + i * 256;
        if (attn_out) attn_out[idx] = a;
        if (ahi) ahi[idx] = __float2half_rn(a);
    }
}

// ---------------------------------------------------------------------------
extern "C" void kernel_launch(void* const* d_in, const int* in_sizes, int n_in,
                              void* d_out, int out_size)
{
    const float* q  = (const float*)d_in[0];
    const float* k  = (const float*)d_in[1];
    const float* v  = (const float*)d_in[2];
    const float* pe = (const float*)d_in[3];
    const float* Uq = (const float*)d_in[4];
    const float* Uk = (const float*)d_in[5];
    float* out = (float*)d_out;

    __half *qhi, *khi, *vthi, *ahi;
    __half *pehi, *uqt, *ukt, *qpe, *kpe;
    float *bias, *scores;
    cudaGetSymbolAddress((void**)&qhi,  g_qhi);
    cudaGetSymbolAddress((void**)&khi,  g_khi);
    cudaGetSymbolAddress((void**)&vthi, g_vthi);  cudaGetSymbolAddress((void**)&ahi,  g_ahi);
    cudaGetSymbolAddress((void**)&pehi, g_pehi);
    cudaGetSymbolAddress((void**)&uqt,  g_uqt);   cudaGetSymbolAddress((void**)&ukt,  g_ukt);
    cudaGetSymbolAddress((void**)&qpe,  g_qpe);   cudaGetSymbolAddress((void**)&kpe,  g_kpe);
    cudaGetSymbolAddress((void**)&bias, g_bias);  cudaGetSymbolAddress((void**)&scores, g_scores);

    const float invScale = 1.0f / 11.313708498984761f;  // 1/sqrt(2*64)

    const long long ctxElems  = (long long)NB * SEQ * DM;
    const long long attnElems = (long long)NB * SEQ * SEQ;
    float* ctxOut  = out;
    float* attnOut = nullptr;
    if ((long long)out_size == ctxElems + attnElems) {
        attnOut = out + ctxElems;
    } else if ((long long)out_size == attnElems) {
        attnOut = out; ctxOut = nullptr;
    }

    const int SM1 = 2 * 2 * 128 * 80;   // 40960 B (2 stages x 2 tiles)
    cudaFuncSetAttribute(hgemm<0>, cudaFuncAttributeMaxDynamicSharedMemorySize, SM1);
    cudaFuncSetAttribute(hgemm<1>, cudaFuncAttributeMaxDynamicSharedMemorySize, SM1);

    // ---- converts (4x-ILP: grid = n4/1024) ----
    split_k<<<(int)(NQ / 4 / 1024), 256>>>((const float4*)q, qhi, (int)(NQ / 4));
    split_k<<<(int)(NQ / 4 / 1024), 256>>>((const float4*)k, khi, (int)(NQ / 4));
    split_k<<<(int)(NP / 4 / 1024), 256>>>((const float4*)pe, pehi, (int)(NP / 4));
    tsplit_k<<<dim3(DM / 32, DM / 32, 1), dim3(32, 8)>>>(Uq, uqt, DM, DM, 0, 0);
    tsplit_k<<<dim3(DM / 32, DM / 32, 1), dim3(32, 8)>>>(Uk, ukt, DM, DM, 0, 0);
    if (ctxOut)
        tsplit_k<<<dim3(DM / 32, SEQ / 32, NB), dim3(32, 8)>>>(
            v, vthi, SEQ, DM, (long long)SEQ * DM, (long long)SEQ * DM);

    // ---- TUPE bias chain (single-pass fp16) ----
    hgemm<1><<<dim3(DM / 128, SEQ / 128, 1), 256, SM1>>>(
        pehi, uqt, qpe, nullptr, DM, DM, 0, 0, 0, 1.f);
    hgemm<1><<<dim3(DM / 128, SEQ / 128, 1), 256, SM1>>>(
        pehi, ukt, kpe, nullptr, DM, DM, 0, 0, 0, 1.f);
    hgemm<0><<<dim3(SEQ / 128, SEQ / 128, 1), 256, SM1>>>(
        qpe, kpe, bias, nullptr, DM, SEQ, 0, 0, 0, 1.f);

    // ---- scores = (q @ k^T + bias) * invScale  (single-pass fp16) ----
    hgemm<0><<<dim3(SEQ / 128, SEQ / 128, NB), 256, SM1>>>(
        qhi, khi, scores, bias, DM, SEQ,
        (long long)SEQ * DM, (long long)SEQ * DM, (long long)SEQ * SEQ, invScale);

    // ---- softmax (emits attn fp32 and/or fp16) ----
    softmax_kernel<<<NB * SEQ, 256>>>(scores, attnOut, ctxOut ? ahi : nullptr);

    // ---- ctx^T = v^T @ attn^T  (single-pass fp16, row-major out == swapaxes) ----
    if (ctxOut)
        hgemm<0><<<dim3(SEQ / 128, DM / 128, NB), 256, SM1>>>(
            vthi, ahi, ctxOut, nullptr, SEQ, SEQ,
            (long long)SEQ * DM, (long long)SEQ * SEQ, (long long)SEQ * DM, 1.f);
}